// round 2
// baseline (speedup 1.0000x reference)
#include <cuda_runtime.h>
#include <math.h>

#define V_TOT 262144
#define G_TOT 4096
#define NFEAT 256
#define GFEAT 256
#define CHUNK 1024

// ---------------- scratch (no allocation allowed) ----------------
__device__ int   d_seg_start[G_TOT + 1];
__device__ float d_ctx_nf[G_TOT * GFEAT];        // sum_v a_v * node_feats[v]
__device__ float d_context[G_TOT * GFEAT];       // elu(ctx_nf @ Wp^T + bp)
__device__ float d_gi[G_TOT * 3 * GFEAT];
__device__ float d_gh[G_TOT * 3 * GFEAT];

// ---------------- kernel 0: segment boundaries (sorted ids) ------
__global__ void seg_bounds_kernel(const int* __restrict__ seg) {
    int g = blockIdx.x * blockDim.x + threadIdx.x;
    if (g > G_TOT) return;
    if (g == G_TOT) { d_seg_start[G_TOT] = V_TOT; return; }
    int lo = 0, hi = V_TOT;
    while (lo < hi) {
        int mid = (lo + hi) >> 1;
        if (seg[mid] < g) lo = mid + 1; else hi = mid;
    }
    d_seg_start[g] = lo;
}

// ---------------- block reduce helper (256 threads, 8 warps) -----
__device__ __forceinline__ float block_reduce(float v, float* s_red, float* s_bcast, int is_max) {
    #pragma unroll
    for (int o = 16; o > 0; o >>= 1) {
        float oth = __shfl_down_sync(0xffffffffu, v, o);
        v = is_max ? fmaxf(v, oth) : (v + oth);
    }
    int lane = threadIdx.x & 31, w = threadIdx.x >> 5;
    if (lane == 0) s_red[w] = v;
    __syncthreads();
    if (w == 0) {
        float a = (lane < 8) ? s_red[lane] : (is_max ? -INFINITY : 0.0f);
        #pragma unroll
        for (int o = 4; o > 0; o >>= 1) {
            float oth = __shfl_down_sync(0xffffffffu, a, o);
            a = is_max ? fmaxf(a, oth) : (a + oth);
        }
        if (lane == 0) *s_bcast = a;
    }
    __syncthreads();
    return *s_bcast;
}

// ---------------- kernel 1: attention pool (one block per graph) --
// Computes d_ctx_nf[g] = sum_v softmax_v(z) * node_feats[v]
// z_v = leaky_relu(nf[v] . Wl[256:512] + relu(gf[g]) . Wl[0:256] + bl)
__global__ void pool_kernel(const float* __restrict__ nf,
                            const float* __restrict__ gfeat,
                            const float* __restrict__ Wl,
                            const float* __restrict__ bl) {
    __shared__ float s_wl[NFEAT];
    __shared__ float s_z[CHUNK];
    __shared__ float s_red[8];
    __shared__ float s_bcast;

    int g = blockIdx.x;
    int t = threadIdx.x;
    int lane = t & 31, warp = t >> 5;

    // node-part of logit weights
    s_wl[t] = Wl[NFEAT + t];

    // per-graph logit constant c_g
    float gv = gfeat[(size_t)g * GFEAT + t];
    gv = gv > 0.0f ? gv : 0.0f;
    float c = block_reduce(gv * Wl[t], s_red, &s_bcast, 0) + bl[0];

    int s = d_seg_start[g], e = d_seg_start[g + 1];

    float m = -INFINITY, denom = 0.0f, acc = 0.0f;

    for (int base = s; base < e; base += CHUNK) {
        int n = min(CHUNK, e - base);

        // phase A: logits for this chunk (warp per node)
        for (int i = warp; i < n; i += 8) {
            const float* row = nf + (size_t)(base + i) * NFEAT;
            float p = 0.0f;
            #pragma unroll
            for (int j = 0; j < 8; j++)
                p += row[lane + 32 * j] * s_wl[lane + 32 * j];
            #pragma unroll
            for (int o = 16; o > 0; o >>= 1)
                p += __shfl_down_sync(0xffffffffu, p, o);
            if (lane == 0) {
                float zr = p + c;
                s_z[i] = (zr >= 0.0f) ? zr : 0.01f * zr;
            }
        }
        __syncthreads();

        // chunk max
        float lm = -INFINITY;
        for (int i = t; i < n; i += 256) lm = fmaxf(lm, s_z[i]);
        float cm = block_reduce(lm, s_red, &s_bcast, 1);
        float nm = fmaxf(m, cm);
        float sf = (m == -INFINITY) ? 0.0f : expf(m - nm);

        // chunk denom + replace z with exp(z - nm)
        float ld = 0.0f;
        for (int i = t; i < n; i += 256) {
            float ev = expf(s_z[i] - nm);
            s_z[i] = ev;
            ld += ev;
        }
        float cd = block_reduce(ld, s_red, &s_bcast, 0);
        denom = denom * sf + cd;

        // accumulate weighted features: thread t owns feature column t
        float a2 = acc * sf;
        int i = 0;
        for (; i + 4 <= n; i += 4) {
            a2 += s_z[i + 0] * nf[(size_t)(base + i + 0) * NFEAT + t];
            a2 += s_z[i + 1] * nf[(size_t)(base + i + 1) * NFEAT + t];
            a2 += s_z[i + 2] * nf[(size_t)(base + i + 2) * NFEAT + t];
            a2 += s_z[i + 3] * nf[(size_t)(base + i + 3) * NFEAT + t];
        }
        for (; i < n; i++)
            a2 += s_z[i] * nf[(size_t)(base + i) * NFEAT + t];
        acc = a2;
        m = nm;
        __syncthreads();  // protect s_z before next chunk
    }

    d_ctx_nf[(size_t)g * GFEAT + t] = (e > s) ? (acc / denom) : 0.0f;
}

// ---------------- kernel 2: tiled SGEMM  Out = act(A @ W^T + bias) ---
// A: [M,K] row-major, W: [N,K] row-major, Out: [M,N]. BM=BN=64, BK=16.
// act: 0 = identity, 1 = elu
__global__ void gemm_kernel(const float* __restrict__ A,
                            const float* __restrict__ W,
                            const float* __restrict__ bias,
                            float* __restrict__ Out,
                            int N, int K, int act) {
    __shared__ float As[16][64];
    __shared__ float Bs[16][64];

    int row0 = blockIdx.y * 64;
    int col0 = blockIdx.x * 64;
    int tx = threadIdx.x & 15;   // 0..15 -> 4 cols
    int ty = threadIdx.x >> 4;   // 0..15 -> 4 rows

    int mg = threadIdx.x >> 2;   // 0..63 (row within tile for loads)
    int kq = threadIdx.x & 3;    // 0..3  (float4 within 16-wide k)

    float accv[4][4];
    #pragma unroll
    for (int i = 0; i < 4; i++)
        #pragma unroll
        for (int j = 0; j < 4; j++) accv[i][j] = 0.0f;

    for (int kb = 0; kb < K; kb += 16) {
        float4 a4 = *(const float4*)(A + (size_t)(row0 + mg) * K + kb + kq * 4);
        float4 b4 = *(const float4*)(W + (size_t)(col0 + mg) * K + kb + kq * 4);
        As[kq * 4 + 0][mg] = a4.x; As[kq * 4 + 1][mg] = a4.y;
        As[kq * 4 + 2][mg] = a4.z; As[kq * 4 + 3][mg] = a4.w;
        Bs[kq * 4 + 0][mg] = b4.x; Bs[kq * 4 + 1][mg] = b4.y;
        Bs[kq * 4 + 2][mg] = b4.z; Bs[kq * 4 + 3][mg] = b4.w;
        __syncthreads();

        #pragma unroll
        for (int k = 0; k < 16; k++) {
            float a[4], b[4];
            #pragma unroll
            for (int i = 0; i < 4; i++) a[i] = As[k][ty * 4 + i];
            #pragma unroll
            for (int j = 0; j < 4; j++) b[j] = Bs[k][tx * 4 + j];
            #pragma unroll
            for (int i = 0; i < 4; i++)
                #pragma unroll
                for (int j = 0; j < 4; j++)
                    accv[i][j] += a[i] * b[j];
        }
        __syncthreads();
    }

    #pragma unroll
    for (int i = 0; i < 4; i++) {
        int rr = row0 + ty * 4 + i;
        #pragma unroll
        for (int j = 0; j < 4; j++) {
            int cc = col0 + tx * 4 + j;
            float v = accv[i][j] + bias[cc];
            if (act == 1) v = (v > 0.0f) ? v : expm1f(v);
            Out[(size_t)rr * N + cc] = v;
        }
    }
}

// ---------------- kernel 3: GRU gates -------------------------------
__global__ void gru_kernel(const float* __restrict__ gfeat, float* __restrict__ out) {
    int idx = blockIdx.x * blockDim.x + threadIdx.x;
    if (idx >= G_TOT * GFEAT) return;
    int g = idx >> 8, j = idx & 255;
    const float* gi = d_gi + (size_t)g * 768;
    const float* gh = d_gh + (size_t)g * 768;
    float r = 1.0f / (1.0f + expf(-(gi[j] + gh[j])));
    float u = 1.0f / (1.0f + expf(-(gi[256 + j] + gh[256 + j])));
    float n = tanhf(gi[512 + j] + r * gh[512 + j]);
    out[idx] = (1.0f - u) * n + u * gfeat[idx];
}

// ---------------- launch --------------------------------------------
extern "C" void kernel_launch(void* const* d_in, const int* in_sizes, int n_in,
                              void* d_out, int out_size) {
    const float* node_feats = (const float*)d_in[0];
    const float* g_feats    = (const float*)d_in[1];
    const int*   seg        = (const int*)  d_in[2];
    const float* Wl         = (const float*)d_in[3];
    const float* bl         = (const float*)d_in[4];
    const float* Wp         = (const float*)d_in[5];
    const float* bp         = (const float*)d_in[6];
    const float* W_ih       = (const float*)d_in[7];
    const float* W_hh       = (const float*)d_in[8];
    const float* b_ih       = (const float*)d_in[9];
    const float* b_hh       = (const float*)d_in[10];
    float* out = (float*)d_out;

    float *p_ctx_nf, *p_context, *p_gi, *p_gh;
    cudaGetSymbolAddress((void**)&p_ctx_nf,  d_ctx_nf);
    cudaGetSymbolAddress((void**)&p_context, d_context);
    cudaGetSymbolAddress((void**)&p_gi,      d_gi);
    cudaGetSymbolAddress((void**)&p_gh,      d_gh);

    seg_bounds_kernel<<<(G_TOT + 1 + 255) / 256, 256>>>(seg);
    pool_kernel<<<G_TOT, 256>>>(node_feats, g_feats, Wl, bl);
    // context = elu(ctx_nf @ Wp^T + bp)
    gemm_kernel<<<dim3(GFEAT / 64, G_TOT / 64), 256>>>(p_ctx_nf, Wp, bp, p_context,
                                                       GFEAT, NFEAT, 1);
    // gi = context @ W_ih^T + b_ih
    gemm_kernel<<<dim3(768 / 64, G_TOT / 64), 256>>>(p_context, W_ih, b_ih, p_gi,
                                                     768, GFEAT, 0);
    // gh = g_feats @ W_hh^T + b_hh
    gemm_kernel<<<dim3(768 / 64, G_TOT / 64), 256>>>(g_feats, W_hh, b_hh, p_gh,
                                                     768, GFEAT, 0);
    gru_kernel<<<(G_TOT * GFEAT + 255) / 256, 256>>>(g_feats, out);
}

// round 3
// speedup vs baseline: 1.1298x; 1.1298x over previous
#include <cuda_runtime.h>
#include <math.h>

#define V_TOT 262144
#define G_TOT 4096
#define NFEAT 256
#define GFEAT 256

typedef unsigned long long ull;

// ---------------- scratch (no allocation allowed) ----------------
__device__ int   d_seg_start[G_TOT + 1];
__device__ float d_ctx_nf[G_TOT * GFEAT];        // sum_v a_v * node_feats[v]
__device__ float d_context[G_TOT * GFEAT];       // elu(ctx_nf @ Wp^T + bp)
__device__ float d_gi[G_TOT * 3 * GFEAT];
__device__ float d_gh[G_TOT * 3 * GFEAT];

// ---------------- kernel 0: segment boundaries (sorted ids) ------
__global__ void seg_bounds_kernel(const int* __restrict__ seg) {
    int g = blockIdx.x * blockDim.x + threadIdx.x;
    if (g > G_TOT) return;
    if (g == G_TOT) { d_seg_start[G_TOT] = V_TOT; return; }
    int lo = 0, hi = V_TOT;
    while (lo < hi) {
        int mid = (lo + hi) >> 1;
        if (seg[mid] < g) lo = mid + 1; else hi = mid;
    }
    d_seg_start[g] = lo;
}

// ---------------- block reduce (sum, 256 threads) ----------------
__device__ __forceinline__ float block_reduce_sum(float v, float* s_red, float* s_bcast) {
    #pragma unroll
    for (int o = 16; o > 0; o >>= 1)
        v += __shfl_down_sync(0xffffffffu, v, o);
    int lane = threadIdx.x & 31, w = threadIdx.x >> 5;
    if (lane == 0) s_red[w] = v;
    __syncthreads();
    if (w == 0) {
        float a = (lane < 8) ? s_red[lane] : 0.0f;
        #pragma unroll
        for (int o = 4; o > 0; o >>= 1)
            a += __shfl_down_sync(0xffffffffu, a, o);
        if (lane == 0) *s_bcast = a;
    }
    __syncthreads();
    return *s_bcast;
}

// ---------------- kernel 1: attention pool (one block per graph) --
// Single pass: warp-per-node. z = leaky_relu(nf.wl_node + c_g); no max
// subtraction needed (|z| small). acc += exp(z)*row held in registers.
__global__ void pool_kernel(const float* __restrict__ nf,
                            const float* __restrict__ gfeat,
                            const float* __restrict__ Wl,
                            const float* __restrict__ bl) {
    __shared__ __align__(16) float s_wl[NFEAT];
    __shared__ __align__(16) float s_acc[8][NFEAT];
    __shared__ float s_den[8];
    __shared__ float s_red[8];
    __shared__ float s_bcast;

    int g = blockIdx.x;
    int t = threadIdx.x;
    int lane = t & 31, warp = t >> 5;

    s_wl[t] = Wl[NFEAT + t];

    // per-graph logit constant c_g = relu(gf[g]) . Wl[0:256] + bl
    float gv = fmaxf(gfeat[(size_t)g * GFEAT + t], 0.0f);
    float c = block_reduce_sum(gv * Wl[t], s_red, &s_bcast) + bl[0];
    // (block_reduce's syncthreads also makes s_wl visible)

    const float4* wl4 = (const float4*)s_wl;
    float4 w0 = wl4[lane];
    float4 w1 = wl4[lane + 32];

    int s = d_seg_start[g], e = d_seg_start[g + 1];

    float a0=0.f,a1=0.f,a2=0.f,a3=0.f,a4=0.f,a5=0.f,a6=0.f,a7=0.f;
    float den = 0.f;

    #pragma unroll 2
    for (int i = s + warp; i < e; i += 8) {
        const float4* row = (const float4*)(nf + (size_t)i * NFEAT);
        float4 r0 = row[lane];
        float4 r1 = row[lane + 32];
        float p = r0.x*w0.x + r0.y*w0.y + r0.z*w0.z + r0.w*w0.w
                + r1.x*w1.x + r1.y*w1.y + r1.z*w1.z + r1.w*w1.w;
        #pragma unroll
        for (int o = 16; o > 0; o >>= 1)
            p += __shfl_xor_sync(0xffffffffu, p, o);
        float z = p + c;
        z = (z >= 0.0f) ? z : 0.01f * z;
        float ez = expf(z);
        den += ez;
        a0 += ez * r0.x; a1 += ez * r0.y; a2 += ez * r0.z; a3 += ez * r0.w;
        a4 += ez * r1.x; a5 += ez * r1.y; a6 += ez * r1.z; a7 += ez * r1.w;
    }

    ((float4*)s_acc[warp])[lane]      = make_float4(a0, a1, a2, a3);
    ((float4*)s_acc[warp])[lane + 32] = make_float4(a4, a5, a6, a7);
    if (lane == 0) s_den[warp] = den;
    __syncthreads();

    float acc = 0.f, denom = 0.f;
    #pragma unroll
    for (int w = 0; w < 8; w++) { acc += s_acc[w][t]; denom += s_den[w]; }
    d_ctx_nf[(size_t)g * GFEAT + t] = (e > s) ? (acc / denom) : 0.0f;
}

// ---------------- packed f32x2 FMA helpers ---------------------------
__device__ __forceinline__ ull fma2(ull a, ull b, ull c) {
    ull d;
    asm("fma.rn.f32x2 %0, %1, %2, %3;" : "=l"(d) : "l"(a), "l"(b), "l"(c));
    return d;
}
__device__ __forceinline__ ull dup2(float x) {
    unsigned int b = __float_as_uint(x);
    return ((ull)b << 32) | (ull)b;
}
__device__ __forceinline__ float lo_f(ull u) { return __int_as_float((int)(u & 0xffffffffu)); }
__device__ __forceinline__ float hi_f(ull u) { return __int_as_float((int)(u >> 32)); }

// ---------------- kernel 2: SGEMM via fma.rn.f32x2 -------------------
// Out[M,N] = act(A[M,K] @ W[N,K]^T + bias). A stored DUPLICATED in smem
// so (a,a) packs and (b_j,b_j+1) packs both come straight from shared.
// act: 0 = identity, 1 = elu
template<int BM, int BN, int BK, int TM, int TN>
__global__ void __launch_bounds__(256)
gemm_f32x2(const float* __restrict__ A, const float* __restrict__ W,
           const float* __restrict__ bias, float* __restrict__ Out,
           int N, int K, int act) {
    constexpr int TX = BN / TN;           // threads along N
    constexpr int NT = (BM / TM) * TX;    // == 256
    constexpr int GM = TM / 4, GN = TN / 4;

    __shared__ __align__(16) float Asd[BK][2 * BM];  // duplicated A
    __shared__ __align__(16) float Bs[BK][BN];

    int tid = threadIdx.x;
    int tx = tid % TX, ty = tid / TX;
    int row0 = blockIdx.y * BM, col0 = blockIdx.x * BN;

    ull acc[TM][TN / 2];
    #pragma unroll
    for (int i = 0; i < TM; i++)
        #pragma unroll
        for (int j = 0; j < TN / 2; j++) acc[i][j] = 0ull;

    for (int kb = 0; kb < K; kb += BK) {
        // fill A (duplicated) and B tiles, float4 GMEM loads
        #pragma unroll
        for (int i = tid; i < BM * BK / 4; i += NT) {
            int lr = i / (BK / 4);
            int lk = (i % (BK / 4)) * 4;
            float4 a4 = *(const float4*)(A + (size_t)(row0 + lr) * K + kb + lk);
            *(ull*)&Asd[lk + 0][2 * lr] = dup2(a4.x);
            *(ull*)&Asd[lk + 1][2 * lr] = dup2(a4.y);
            *(ull*)&Asd[lk + 2][2 * lr] = dup2(a4.z);
            *(ull*)&Asd[lk + 3][2 * lr] = dup2(a4.w);
        }
        #pragma unroll
        for (int i = tid; i < BN * BK / 4; i += NT) {
            int lr = i / (BK / 4);
            int lk = (i % (BK / 4)) * 4;
            float4 b4 = *(const float4*)(W + (size_t)(col0 + lr) * K + kb + lk);
            Bs[lk + 0][lr] = b4.x; Bs[lk + 1][lr] = b4.y;
            Bs[lk + 2][lr] = b4.z; Bs[lk + 3][lr] = b4.w;
        }
        __syncthreads();

        #pragma unroll
        for (int k = 0; k < BK; k++) {
            ull ad[TM], bd[TN / 2];
            #pragma unroll
            for (int gm = 0; gm < GM; gm++) {
                int off = 2 * (gm * (BM / 2)) + 8 * ty;
                ulonglong2 v0 = *(const ulonglong2*)&Asd[k][off];
                ulonglong2 v1 = *(const ulonglong2*)&Asd[k][off + 4];
                ad[gm * 4 + 0] = v0.x; ad[gm * 4 + 1] = v0.y;
                ad[gm * 4 + 2] = v1.x; ad[gm * 4 + 3] = v1.y;
            }
            #pragma unroll
            for (int gn = 0; gn < GN; gn++) {
                ulonglong2 w2 = *(const ulonglong2*)&Bs[k][gn * (BN / 2) + 4 * tx];
                bd[gn * 2 + 0] = w2.x; bd[gn * 2 + 1] = w2.y;
            }
            #pragma unroll
            for (int i = 0; i < TM; i++)
                #pragma unroll
                for (int j = 0; j < TN / 2; j++)
                    acc[i][j] = fma2(ad[i], bd[j], acc[i][j]);
        }
        __syncthreads();
    }

    // epilogue
    #pragma unroll
    for (int gm = 0; gm < GM; gm++) {
        #pragma unroll
        for (int i = 0; i < 4; i++) {
            int rr = row0 + gm * (BM / 2) + ty * 4 + i;
            #pragma unroll
            for (int gn = 0; gn < GN; gn++) {
                int cc = col0 + gn * (BN / 2) + tx * 4;
                ull u0 = acc[gm * 4 + i][gn * 2 + 0];
                ull u1 = acc[gm * 4 + i][gn * 2 + 1];
                float4 bia = *(const float4*)(bias + cc);
                float4 v;
                v.x = lo_f(u0) + bia.x; v.y = hi_f(u0) + bia.y;
                v.z = lo_f(u1) + bia.z; v.w = hi_f(u1) + bia.w;
                if (act == 1) {
                    v.x = (v.x > 0.f) ? v.x : expm1f(v.x);
                    v.y = (v.y > 0.f) ? v.y : expm1f(v.y);
                    v.z = (v.z > 0.f) ? v.z : expm1f(v.z);
                    v.w = (v.w > 0.f) ? v.w : expm1f(v.w);
                }
                *(float4*)(Out + (size_t)rr * N + cc) = v;
            }
        }
    }
}

// ---------------- kernel 3: GRU gates (float4) -----------------------
__device__ __forceinline__ float gru1(float ir, float hr, float iz, float hz,
                                      float in_, float hn, float h) {
    float r = 1.0f / (1.0f + expf(-(ir + hr)));
    float u = 1.0f / (1.0f + expf(-(iz + hz)));
    float n = tanhf(in_ + r * hn);
    return (1.0f - u) * n + u * h;
}

__global__ void gru_kernel(const float* __restrict__ gfeat, float* __restrict__ out) {
    int idx = blockIdx.x * blockDim.x + threadIdx.x;   // over G*GF/4 float4s
    if (idx >= G_TOT * GFEAT / 4) return;
    int g = idx >> 6, j4 = idx & 63;
    const float4* gi = (const float4*)(d_gi + (size_t)g * 768);
    const float4* gh = (const float4*)(d_gh + (size_t)g * 768);
    float4 ir = gi[j4],       hr = gh[j4];
    float4 iz = gi[64 + j4],  hz = gh[64 + j4];
    float4 in_ = gi[128 + j4], hn = gh[128 + j4];
    float4 h = ((const float4*)gfeat)[idx];
    float4 o;
    o.x = gru1(ir.x, hr.x, iz.x, hz.x, in_.x, hn.x, h.x);
    o.y = gru1(ir.y, hr.y, iz.y, hz.y, in_.y, hn.y, h.y);
    o.z = gru1(ir.z, hr.z, iz.z, hz.z, in_.z, hn.z, h.z);
    o.w = gru1(ir.w, hr.w, iz.w, hz.w, in_.w, hn.w, h.w);
    ((float4*)out)[idx] = o;
}

// ---------------- launch --------------------------------------------
extern "C" void kernel_launch(void* const* d_in, const int* in_sizes, int n_in,
                              void* d_out, int out_size) {
    const float* node_feats = (const float*)d_in[0];
    const float* g_feats    = (const float*)d_in[1];
    const int*   seg        = (const int*)  d_in[2];
    const float* Wl         = (const float*)d_in[3];
    const float* bl         = (const float*)d_in[4];
    const float* Wp         = (const float*)d_in[5];
    const float* bp         = (const float*)d_in[6];
    const float* W_ih       = (const float*)d_in[7];
    const float* W_hh       = (const float*)d_in[8];
    const float* b_ih       = (const float*)d_in[9];
    const float* b_hh       = (const float*)d_in[10];
    float* out = (float*)d_out;

    float *p_ctx_nf, *p_context, *p_gi, *p_gh;
    cudaGetSymbolAddress((void**)&p_ctx_nf,  d_ctx_nf);
    cudaGetSymbolAddress((void**)&p_context, d_context);
    cudaGetSymbolAddress((void**)&p_gi,      d_gi);
    cudaGetSymbolAddress((void**)&p_gh,      d_gh);

    seg_bounds_kernel<<<(G_TOT + 1 + 255) / 256, 256>>>(seg);

    // gh = g_feats @ W_hh^T + b_hh  (independent of pool -> launch early)
    gemm_f32x2<128, 128, 8, 8, 8><<<dim3(768 / 128, G_TOT / 128), 256>>>(
        g_feats, W_hh, b_hh, p_gh, 768, GFEAT, 0);

    pool_kernel<<<G_TOT, 256>>>(node_feats, g_feats, Wl, bl);

    // context = elu(ctx_nf @ Wp^T + bp)   (64-row tiles -> 128 blocks)
    gemm_f32x2<64, 128, 8, 4, 8><<<dim3(GFEAT / 128, G_TOT / 64), 256>>>(
        p_ctx_nf, Wp, bp, p_context, GFEAT, NFEAT, 1);

    // gi = context @ W_ih^T + b_ih
    gemm_f32x2<128, 128, 8, 8, 8><<<dim3(768 / 128, G_TOT / 128), 256>>>(
        p_context, W_ih, b_ih, p_gi, 768, GFEAT, 0);

    gru_kernel<<<(G_TOT * GFEAT / 4 + 255) / 256, 256>>>(g_feats, out);
}